// round 10
// baseline (speedup 1.0000x reference)
#include <cuda_runtime.h>
#include <cstdint>
#include <cstddef>

// Problem constants
#define KVLEN   4096
#define NEWPOS  4092
#define NSPLIT  8

// Partial buffers: g_po[split][b*8+h][dl*16 + q]
static __device__ float g_po[(size_t)NSPLIT * 256 * 2048];
static __device__ float g_pl[NSPLIT * 256 * 16];
static __device__ int   g_cnt[256];   // per-(b,h) split-arrival counters (self-resetting)

// ---------------- shared memory layout (bytes) ----------------
// K per tile: 2 bufs x 16 rows x 132 floats (pad 4 -> fragment banks 4r+c) = 16896
#define KT_BYTES  (2 * 16 * 132 * 4)
#define OFF_K     0
#define OFF_V     (4 * KT_BYTES)              // 67584
#define VT_BYTES  (16 * 136 * 4)              // 8704 (pad 8 -> fragment banks 8c+r)
#define OFF_P     (OFF_V + 4 * VT_BYTES)      // 102400
#define PW_BYTES  (16 * 8 * 4)                // 512 per warp
#define OFF_RL    (OFF_P + 8 * PW_BYTES)      // 106496
#define SMEM_TOTAL (OFF_RL + 128)             // 106624

__device__ __forceinline__ float ex2f(float x) {
    float y;
    asm("ex2.approx.ftz.f32 %0, %1;" : "=f"(y) : "f"(x));
    return y;
}
__device__ __forceinline__ uint32_t f2tf(float x) {   // round-to-nearest tf32 bits
    uint32_t r;
    asm("cvt.rna.tf32.f32 %0, %1;" : "=r"(r) : "f"(x));
    return r;
}
__device__ __forceinline__ void mma_tf32(float& c0, float& c1, float& c2, float& c3,
                                         uint32_t a0, uint32_t a1, uint32_t a2, uint32_t a3,
                                         uint32_t b0, uint32_t b1) {
    asm("mma.sync.aligned.m16n8k8.row.col.f32.tf32.tf32.f32 "
        "{%0,%1,%2,%3}, {%4,%5,%6,%7}, {%8,%9}, {%0,%1,%2,%3};"
        : "+f"(c0), "+f"(c1), "+f"(c2), "+f"(c3)
        : "r"(a0), "r"(a1), "r"(a2), "r"(a3), "r"(b0), "r"(b1));
}
__device__ __forceinline__ void cp_async16(uint32_t dst, const void* src) {
    asm volatile("cp.async.cg.shared.global [%0], [%1], 16;"
                 :: "r"(dst), "l"(__cvta_generic_to_global(src)) : "memory");
}
__device__ __forceinline__ void cp_commit() {
    asm volatile("cp.async.commit_group;" ::: "memory");
}
__device__ __forceinline__ void cp_wait1() {
    asm volatile("cp.async.wait_group 1;" ::: "memory");
}
__device__ __forceinline__ void cp_wait2() {
    asm volatile("cp.async.wait_group 2;" ::: "memory");
}
__device__ __forceinline__ void bar_pair(int id) {
    asm volatile("bar.sync %0, 64;" :: "r"(id) : "memory");
}

// grid = (NSPLIT, 8, 32), block = 256, 2 CTAs/SM
__global__ void __launch_bounds__(256, 2) attn_main(
    const float* __restrict__ gq,    // (128, 4096)
    const float* __restrict__ gknew, // (128, 1024)
    const float* __restrict__ gvnew, // (128, 1024)
    const float* __restrict__ gkc,   // (8192,16,8,128)
    const float* __restrict__ gvc,
    const int*   __restrict__ gbt,   // (32, 256)
    float*       __restrict__ gout)  // (128, 4096)
{
    extern __shared__ char sm_raw[];
    __shared__ int s_islast;
    const int s    = blockIdx.x;
    const int h    = blockIdx.y;
    const int b    = blockIdx.z;
    const int tid  = threadIdx.x;
    const int warp = tid >> 5;       // 0..7
    const int lane = tid & 31;
    const int tile = warp >> 1;      // 0..3, each tile = 128 tokens
    const int qh   = warp & 1;       // query half (queries qh*8..qh*8+7)
    const int r    = lane >> 2;      // mma groupID
    const int c    = lane & 3;       // mma threadID-in-group
    const int hf   = lane >> 4;

    float* smKf = (float*)(sm_raw + OFF_K + tile * KT_BYTES);  // [buf][16 tok][132]
    float* smVf = (float*)(sm_raw + OFF_V + tile * VT_BYTES);  // [16 tok][136]
    float* smP  = (float*)(sm_raw + OFF_P + warp * PW_BYTES);  // [16 tok][8 q]
    const uint32_t aK = (uint32_t)__cvta_generic_to_shared(smKf);
    const uint32_t aV = (uint32_t)__cvta_generic_to_shared(smVf);

    const int  btidx = b * 256 + s * 32 + tile * 8;   // 8 cache blocks per tile
    const bool tailw = (s == 7 && tile == 3);
    const int  barid = tile + 1;

    // K: warp issues its query-half's 8 rows (gr = qh*8 + rr)
    auto issue_k = [&](int st, int buf, int blk) {
#pragma unroll
        for (int rr = 0; rr < 8; rr++) {
            const int gr = qh * 8 + rr;
            const char* src = (const char*)gkc + (size_t)blk * 65536
                            + (size_t)gr * 4096 + h * 512 + lane * 16;
            if (tailw && st == 7 && gr >= 12)
                src = (const char*)gknew + (size_t)(b * 4 + (gr - 12)) * 4096
                    + h * 512 + lane * 16;
            const uint32_t dst = aK + buf * 8448 + gr * 528 + hf * 256 + ((lane * 16) & 255);
            cp_async16(dst, src);
        }
    };
    // V: half hv (rows 0-7 / 8-15); warp issues 4 rows
    auto issue_v = [&](int hv, int st, int blk) {
#pragma unroll
        for (int rr = 0; rr < 4; rr++) {
            const int vr = hv * 8 + qh * 4 + rr;
            const char* src = (const char*)gvc + (size_t)blk * 65536
                            + (size_t)vr * 4096 + h * 512 + lane * 16;
            if (tailw && st == 7 && vr >= 12)
                src = (const char*)gvnew + (size_t)(b * 4 + (vr - 12)) * 4096
                    + h * 512 + lane * 16;
            cp_async16(aV + vr * 544 + lane * 16, src);
        }
    };

    // -------- prologue: start K0, load Q fragments into registers --------
    int blk_cur = gbt[btidx];
    issue_k(0, 0, blk_cur);
    cp_commit();                                  // pending: [K0]

    // B-fragment of Q (k=dim, n=query): thread owns query q = qh*8 + r,
    // dims 8kc + c and 8kc + c + 4, prescaled by sm_scale*log2e, tf32-rounded.
    uint32_t qreg[16][2];
    {
        const int q    = qh * 8 + r;
        const int qpos = q >> 2, g = q & 3;
        const float SC = 0.08838834764831845f * 1.4426950408889634f;
        const float* qsrc = gq + (size_t)(b * 4 + qpos) * 4096 + (h * 4 + g) * 128;
#pragma unroll
        for (int kc = 0; kc < 16; kc++) {
            qreg[kc][0] = f2tf(qsrc[8 * kc + c] * SC);
            qreg[kc][1] = f2tf(qsrc[8 * kc + 4 + c] * SC);
        }
    }

    // O^T accumulators: 8 d-tiles x 4 regs. o0/o1: dims 16dt+r, qcols 2c/2c+1;
    // o2/o3: dims 16dt+r+8.
    float o0[8], o1[8], o2[8], o3[8];
#pragma unroll
    for (int dt = 0; dt < 8; dt++) { o0[dt] = o1[dt] = o2[dt] = o3[dt] = 0.f; }
    float lacc0 = 0.f, lacc1 = 0.f;   // l for queries qh*8+2c, qh*8+2c+1

    const float* kA0 = smKf + r * 132 + c;        // + buf*2112 floats
    const float* vA0 = smVf + c * 136 + r;

#pragma unroll 1
    for (int st = 0; st < 8; st++) {
        const int buf = st & 1;
        const int blk_next = (st < 7) ? gbt[btidx + st + 1] : 0;

        issue_v(0, st, blk_cur);
        cp_commit();            // pending: [K_st, VA]
        cp_wait1();             // own K_st rows done
        bar_pair(barid);        // K_st tile full (both warps)

        // ---------- QK: S^T = K (16 tok x 128) x Q^T -> 16 tok x 8 q ----------
        float s0 = 0.f, s1 = 0.f, s2 = 0.f, s3 = 0.f;
        float u0 = 0.f, u1 = 0.f, u2 = 0.f, u3 = 0.f;
        const float* kA = kA0 + buf * 2112;
#pragma unroll
        for (int kc = 0; kc < 16; kc += 2) {
            {
                uint32_t a0 = f2tf(kA[kc * 8]);
                uint32_t a1 = f2tf(kA[kc * 8 + 1056]);
                uint32_t a2 = f2tf(kA[kc * 8 + 4]);
                uint32_t a3 = f2tf(kA[kc * 8 + 1060]);
                mma_tf32(s0, s1, s2, s3, a0, a1, a2, a3, qreg[kc][0], qreg[kc][1]);
            }
            {
                uint32_t a0 = f2tf(kA[kc * 8 + 8]);
                uint32_t a1 = f2tf(kA[kc * 8 + 1064]);
                uint32_t a2 = f2tf(kA[kc * 8 + 12]);
                uint32_t a3 = f2tf(kA[kc * 8 + 1068]);
                mma_tf32(u0, u1, u2, u3, a0, a1, a2, a3, qreg[kc + 1][0], qreg[kc + 1][1]);
            }
        }
        s0 += u0; s1 += u1; s2 += u2; s3 += u3;

        issue_v(1, st, blk_cur);
        cp_commit();            // pending: [VA, VB]
        if (st < 7) issue_k(st + 1, buf ^ 1, blk_next);
        cp_commit();            // pending: [VA, VB, K_{st+1} (possibly empty)]

        // ---------- softmax numerator (fixed constant; cancels in o/l) --------
        float p0 = ex2f(s0 - 20.0f);
        float p1 = ex2f(s1 - 20.0f);
        float p2 = ex2f(s2 - 20.0f);   // token r+8
        float p3 = ex2f(s3 - 20.0f);
        if (tailw && st == 7) {
            const int qpos = qh * 2 + (c >> 1);     // same for qcols 2c, 2c+1
            if (r - 4 > qpos) { p2 = 0.f; p3 = 0.f; }   // tokens 12..15
        }
        // tf32-round p BEFORE both l-accumulate and P store -> numer/denom consistent
        const float pf0 = __uint_as_float(f2tf(p0));
        const float pf1 = __uint_as_float(f2tf(p1));
        const float pf2 = __uint_as_float(f2tf(p2));
        const float pf3 = __uint_as_float(f2tf(p3));
        lacc0 += pf0 + pf2;
        lacc1 += pf1 + pf3;
        *(float2*)&smP[r * 8 + 2 * c]       = make_float2(pf0, pf1);
        *(float2*)&smP[(r + 8) * 8 + 2 * c] = make_float2(pf2, pf3);
        __syncwarp();

        cp_wait2();             // VA done (VB, K_{st+1} may fly)
        bar_pair(barid);        // VA full (both warps)

        // ---------- PV chunk A: tokens 0-7 ----------
        {
            const uint32_t b0 = __float_as_uint(smP[c * 8 + r]);
            const uint32_t b1 = __float_as_uint(smP[(c + 4) * 8 + r]);
#pragma unroll
            for (int dt = 0; dt < 8; dt++) {
                uint32_t a0 = f2tf(vA0[16 * dt]);
                uint32_t a1 = f2tf(vA0[16 * dt + 8]);
                uint32_t a2 = f2tf(vA0[544 + 16 * dt]);
                uint32_t a3 = f2tf(vA0[544 + 16 * dt + 8]);
                mma_tf32(o0[dt], o1[dt], o2[dt], o3[dt], a0, a1, a2, a3, b0, b1);
            }
        }

        cp_wait1();             // VB done (K_{st+1} may fly)
        bar_pair(barid);        // VB full (both warps)

        // ---------- PV chunk B: tokens 8-15 ----------
        {
            const uint32_t b0 = __float_as_uint(smP[64 + c * 8 + r]);
            const uint32_t b1 = __float_as_uint(smP[64 + (c + 4) * 8 + r]);
#pragma unroll
            for (int dt = 0; dt < 8; dt++) {
                uint32_t a0 = f2tf(vA0[1088 + 16 * dt]);
                uint32_t a1 = f2tf(vA0[1088 + 16 * dt + 8]);
                uint32_t a2 = f2tf(vA0[1632 + 16 * dt]);
                uint32_t a3 = f2tf(vA0[1632 + 16 * dt + 8]);
                mma_tf32(o0[dt], o1[dt], o2[dt], o3[dt], a0, a1, a2, a3, b0, b1);
            }
        }
        blk_cur = blk_next;
    }

    // ---------- finalize l: reduce across token-groups (lanes with same c) ----------
#pragma unroll
    for (int off = 4; off <= 16; off <<= 1) {
        lacc0 += __shfl_xor_sync(0xffffffffu, lacc0, off);
        lacc1 += __shfl_xor_sync(0xffffffffu, lacc1, off);
    }

    // ---------- cross-tile tree reduce (4 -> 1), per query-half ----------
    __syncthreads();
    float4* redo4 = (float4*)(sm_raw + OFF_K);   // dead K smem
    float*  redl  = (float*)(sm_raw + OFF_RL);
    for (int half = 2; half >= 1; half >>= 1) {
        if (tile >= half && tile < 2 * half) {
            const int idx = (tile - half) * 2 + qh;
#pragma unroll
            for (int dt = 0; dt < 8; dt++)
                redo4[(idx * 8 + dt) * 32 + lane] = make_float4(o0[dt], o1[dt], o2[dt], o3[dt]);
            if (lane < 4)
                *(float2*)&redl[idx * 8 + lane * 2] = make_float2(lacc0, lacc1);
        }
        __syncthreads();
        if (tile < half) {
            const int idx = tile * 2 + qh;
#pragma unroll
            for (int dt = 0; dt < 8; dt++) {
                float4 x = redo4[(idx * 8 + dt) * 32 + lane];
                o0[dt] += x.x; o1[dt] += x.y; o2[dt] += x.z; o3[dt] += x.w;
            }
            lacc0 += redl[idx * 8 + c * 2];
            lacc1 += redl[idx * 8 + c * 2 + 1];
        }
        __syncthreads();
    }

    // ---------- write per-split partials (warps 0 and 1) ----------
    const int bh = b * 8 + h;
    if (tile == 0) {
        const size_t base = ((size_t)(s * 256) + bh) * 2048;
#pragma unroll
        for (int dt = 0; dt < 8; dt++) {
            const int d0 = 16 * dt + r;
            *(float2*)&g_po[base + (size_t)d0 * 16 + qh * 8 + 2 * c] =
                make_float2(o0[dt], o1[dt]);
            *(float2*)&g_po[base + (size_t)(d0 + 8) * 16 + qh * 8 + 2 * c] =
                make_float2(o2[dt], o3[dt]);
        }
        if (lane < 4)
            *(float2*)&g_pl[(s * 256 + bh) * 16 + qh * 8 + 2 * lane] =
                make_float2(lacc0, lacc1);
    }

    // ---------- fused combine: last split CTA for this (b,h) finishes it ----------
    __threadfence();
    __syncthreads();
    if (tid == 0)
        s_islast = (atomicAdd(&g_cnt[bh], 1) == NSPLIT - 1);
    __syncthreads();
    if (!s_islast) return;
    __threadfence();

    // 1/l per query (16 values) into smem
    float* sml = (float*)(sm_raw + OFF_RL);
    if (tid < 16) {
        float l = 0.f;
#pragma unroll
        for (int ss = 0; ss < NSPLIT; ss++)
            l += g_pl[ss * 4096 + bh * 16 + tid];
        sml[tid] = 1.0f / l;
    }
    __syncthreads();

    // each thread: 8 consecutive elems (e = dl*16 + qq), float4 loads per split
    {
        const int e0 = tid * 8;               // dl = e0>>4 fixed; qq = (e0&15)+j
        const int dl = e0 >> 4;
        const int q0 = e0 & 15;               // 0 or 8
        float acc[8];
#pragma unroll
        for (int j = 0; j < 8; j++) acc[j] = 0.f;
#pragma unroll
        for (int ss = 0; ss < NSPLIT; ss++) {
            const float* pp = &g_po[(size_t)ss * 524288 + (size_t)bh * 2048 + e0];
            float4 x = *(const float4*)(pp);
            float4 y = *(const float4*)(pp + 4);
            acc[0] += x.x; acc[1] += x.y; acc[2] += x.z; acc[3] += x.w;
            acc[4] += y.x; acc[5] += y.y; acc[6] += y.z; acc[7] += y.w;
        }
#pragma unroll
        for (int j = 0; j < 8; j++) {
            const int qq = q0 + j;
            const int qpos = qq >> 2, g = qq & 3;
            gout[(size_t)(b * 4 + qpos) * 4096 + (h * 4 + g) * 128 + dl] =
                acc[j] * sml[qq];
        }
    }
    if (tid == 0) g_cnt[bh] = 0;   // reset for next launch (graph replay safe)
}

extern "C" void kernel_launch(void* const* d_in, const int* in_sizes, int n_in,
                              void* d_out, int out_size)
{
    const float* q   = (const float*)d_in[0];
    const float* k   = (const float*)d_in[1];
    const float* v   = (const float*)d_in[2];
    const float* kc  = (const float*)d_in[3];
    const float* vc  = (const float*)d_in[4];
    const int*   bt  = (const int*)d_in[5];
    (void)in_sizes; (void)n_in; (void)out_size;

    cudaFuncSetAttribute(attn_main, cudaFuncAttributeMaxDynamicSharedMemorySize, SMEM_TOTAL);
    attn_main<<<dim3(NSPLIT, 8, 32), 256, SMEM_TOTAL>>>(q, k, v, kc, vc, bt, (float*)d_out);
}

// round 14
// speedup vs baseline: 1.0755x; 1.0755x over previous
#include <cuda_runtime.h>
#include <cstdint>
#include <cstddef>

// Problem constants
#define KVLEN   4096
#define NEWPOS  4092
#define NSPLIT  8

// Partial buffers: g_po[split][b*8+h][dl*16 + q]
static __device__ float g_po[(size_t)NSPLIT * 256 * 2048];
static __device__ float g_pl[NSPLIT * 256 * 16];

// ---------------- shared memory layout (bytes) ----------------
// K per tile: 2 bufs x 16 rows x 132 floats (pad 4 -> fragment banks 4r+c) = 16896
#define KT_BYTES  (2 * 16 * 132 * 4)
#define OFF_K     0
#define OFF_V     (4 * KT_BYTES)              // 67584
#define VT_BYTES  (16 * 136 * 4)              // 8704 (pad 8 -> fragment banks 8c+r)
#define OFF_P     (OFF_V + 4 * VT_BYTES)      // 102400
#define PW_BYTES  (16 * 8 * 4)                // 512 per warp
#define OFF_RL    (OFF_P + 8 * PW_BYTES)      // 106496
#define SMEM_TOTAL (OFF_RL + 128)             // 106624

__device__ __forceinline__ float ex2f(float x) {
    float y;
    asm("ex2.approx.ftz.f32 %0, %1;" : "=f"(y) : "f"(x));
    return y;
}
__device__ __forceinline__ uint32_t f2tf(float x) {   // round-to-nearest tf32 bits
    uint32_t r;
    asm("cvt.rna.tf32.f32 %0, %1;" : "=r"(r) : "f"(x));
    return r;
}
__device__ __forceinline__ void mma_tf32(float& c0, float& c1, float& c2, float& c3,
                                         uint32_t a0, uint32_t a1, uint32_t a2, uint32_t a3,
                                         uint32_t b0, uint32_t b1) {
    asm("mma.sync.aligned.m16n8k8.row.col.f32.tf32.tf32.f32 "
        "{%0,%1,%2,%3}, {%4,%5,%6,%7}, {%8,%9}, {%0,%1,%2,%3};"
        : "+f"(c0), "+f"(c1), "+f"(c2), "+f"(c3)
        : "r"(a0), "r"(a1), "r"(a2), "r"(a3), "r"(b0), "r"(b1));
}
__device__ __forceinline__ void cp_async16(uint32_t dst, const void* src) {
    asm volatile("cp.async.cg.shared.global [%0], [%1], 16;"
                 :: "r"(dst), "l"(__cvta_generic_to_global(src)) : "memory");
}
__device__ __forceinline__ void cp_commit() {
    asm volatile("cp.async.commit_group;" ::: "memory");
}
__device__ __forceinline__ void cp_wait1() {
    asm volatile("cp.async.wait_group 1;" ::: "memory");
}
__device__ __forceinline__ void cp_wait2() {
    asm volatile("cp.async.wait_group 2;" ::: "memory");
}
__device__ __forceinline__ void bar_pair(int id) {
    asm volatile("bar.sync %0, 64;" :: "r"(id) : "memory");
}

// grid = (NSPLIT, 8, 32), block = 256, 2 CTAs/SM
__global__ void __launch_bounds__(256, 2) attn_main(
    const float* __restrict__ gq,    // (128, 4096)
    const float* __restrict__ gknew, // (128, 1024)
    const float* __restrict__ gvnew, // (128, 1024)
    const float* __restrict__ gkc,   // (8192,16,8,128)
    const float* __restrict__ gvc,
    const int*   __restrict__ gbt)   // (32, 256)
{
    extern __shared__ char sm_raw[];
    const int s    = blockIdx.x;
    const int h    = blockIdx.y;
    const int b    = blockIdx.z;
    const int tid  = threadIdx.x;
    const int warp = tid >> 5;       // 0..7
    const int lane = tid & 31;
    const int tile = warp >> 1;      // 0..3, each tile = 128 tokens
    const int qh   = warp & 1;       // query half (queries qh*8..qh*8+7)
    const int r    = lane >> 2;      // mma groupID
    const int c    = lane & 3;       // mma threadID-in-group
    const int hf   = lane >> 4;

    float* smKf = (float*)(sm_raw + OFF_K + tile * KT_BYTES);  // [buf][16 tok][132]
    float* smVf = (float*)(sm_raw + OFF_V + tile * VT_BYTES);  // [16 tok][136]
    float* smP  = (float*)(sm_raw + OFF_P + warp * PW_BYTES);  // [16 tok][8 q]
    const uint32_t aK = (uint32_t)__cvta_generic_to_shared(smKf);
    const uint32_t aV = (uint32_t)__cvta_generic_to_shared(smVf);

    const int  btidx = b * 256 + s * 32 + tile * 8;   // 8 cache blocks per tile
    const bool tailw = (s == 7 && tile == 3);
    const int  barid = tile + 1;

    // K: warp issues its query-half's 8 rows (gr = qh*8 + rr)
    auto issue_k = [&](int st, int buf, int blk) {
#pragma unroll
        for (int rr = 0; rr < 8; rr++) {
            const int gr = qh * 8 + rr;
            const char* src = (const char*)gkc + (size_t)blk * 65536
                            + (size_t)gr * 4096 + h * 512 + lane * 16;
            if (tailw && st == 7 && gr >= 12)
                src = (const char*)gknew + (size_t)(b * 4 + (gr - 12)) * 4096
                    + h * 512 + lane * 16;
            const uint32_t dst = aK + buf * 8448 + gr * 528 + hf * 256 + ((lane * 16) & 255);
            cp_async16(dst, src);
        }
    };
    // V: half hv (rows 0-7 / 8-15); warp issues 4 rows
    auto issue_v = [&](int hv, int st, int blk) {
#pragma unroll
        for (int rr = 0; rr < 4; rr++) {
            const int vr = hv * 8 + qh * 4 + rr;
            const char* src = (const char*)gvc + (size_t)blk * 65536
                            + (size_t)vr * 4096 + h * 512 + lane * 16;
            if (tailw && st == 7 && vr >= 12)
                src = (const char*)gvnew + (size_t)(b * 4 + (vr - 12)) * 4096
                    + h * 512 + lane * 16;
            cp_async16(aV + vr * 544 + lane * 16, src);
        }
    };

    // -------- prologue: start K0 + VA0, load Q fragments into registers --------
    int blk_cur = gbt[btidx];
    issue_k(0, 0, blk_cur);
    cp_commit();                                  // pending: [K0]
    issue_v(0, 0, blk_cur);
    cp_commit();                                  // pending: [K0, VA0]

    // B-fragment of Q (k=dim, n=query): thread owns query q = qh*8 + r,
    // dims 8kc + c and 8kc + c + 4, prescaled by sm_scale*log2e, tf32-rounded.
    uint32_t qreg[16][2];
    {
        const int q    = qh * 8 + r;
        const int qpos = q >> 2, g = q & 3;
        const float SC = 0.08838834764831845f * 1.4426950408889634f;
        const float* qsrc = gq + (size_t)(b * 4 + qpos) * 4096 + (h * 4 + g) * 128;
#pragma unroll
        for (int kc = 0; kc < 16; kc++) {
            qreg[kc][0] = f2tf(qsrc[8 * kc + c] * SC);
            qreg[kc][1] = f2tf(qsrc[8 * kc + 4 + c] * SC);
        }
    }

    // O^T accumulators: 8 d-tiles x 4 regs. o0/o1: dims 16dt+r, qcols 2c/2c+1;
    // o2/o3: dims 16dt+r+8.
    float o0[8], o1[8], o2[8], o3[8];
#pragma unroll
    for (int dt = 0; dt < 8; dt++) { o0[dt] = o1[dt] = o2[dt] = o3[dt] = 0.f; }
    float lacc0 = 0.f, lacc1 = 0.f;   // l for queries qh*8+2c, qh*8+2c+1

    const float* kA0 = smKf + r * 132 + c;        // + buf*2112 floats
    const float* vA0 = smVf + c * 136 + r;

    // Loop invariant at top of st: pending cp groups = [K_st, VA_st]
#pragma unroll 2
    for (int st = 0; st < 8; st++) {
        const int buf = st & 1;
        const int blk_next = (st < 7) ? gbt[btidx + st + 1] : 0;

        cp_wait1();             // K_st done (VA_st may fly)
        bar_pair(barid);        // K_st tile full (both warps)

        // ---------- QK: S^T = K (16 tok x 128) x Q^T -> 16 tok x 8 q ----------
        float s0 = 0.f, s1 = 0.f, s2 = 0.f, s3 = 0.f;
        float u0 = 0.f, u1 = 0.f, u2 = 0.f, u3 = 0.f;
        const float* kA = kA0 + buf * 2112;
#pragma unroll
        for (int kc = 0; kc < 16; kc += 2) {
            {
                uint32_t a0 = f2tf(kA[kc * 8]);
                uint32_t a1 = f2tf(kA[kc * 8 + 1056]);
                uint32_t a2 = f2tf(kA[kc * 8 + 4]);
                uint32_t a3 = f2tf(kA[kc * 8 + 1060]);
                mma_tf32(s0, s1, s2, s3, a0, a1, a2, a3, qreg[kc][0], qreg[kc][1]);
            }
            {
                uint32_t a0 = f2tf(kA[kc * 8 + 8]);
                uint32_t a1 = f2tf(kA[kc * 8 + 1064]);
                uint32_t a2 = f2tf(kA[kc * 8 + 12]);
                uint32_t a3 = f2tf(kA[kc * 8 + 1068]);
                mma_tf32(u0, u1, u2, u3, a0, a1, a2, a3, qreg[kc + 1][0], qreg[kc + 1][1]);
            }
        }
        s0 += u0; s1 += u1; s2 += u2; s3 += u3;

        issue_v(1, st, blk_cur);
        cp_commit();            // pending: [VA, VB]
        if (st < 7) issue_k(st + 1, buf ^ 1, blk_next);
        cp_commit();            // pending: [VA, VB, K_{st+1} (possibly empty)]

        // ---------- softmax numerator (fixed constant; cancels in o/l) --------
        float p0 = ex2f(s0 - 20.0f);
        float p1 = ex2f(s1 - 20.0f);
        float p2 = ex2f(s2 - 20.0f);   // token r+8
        float p3 = ex2f(s3 - 20.0f);
        if (tailw && st == 7) {
            const int qpos = qh * 2 + (c >> 1);     // same for qcols 2c, 2c+1
            if (r - 4 > qpos) { p2 = 0.f; p3 = 0.f; }   // tokens 12..15
        }
        // tf32-round p BEFORE both l-accumulate and P store -> numer/denom consistent
        const float pf0 = __uint_as_float(f2tf(p0));
        const float pf1 = __uint_as_float(f2tf(p1));
        const float pf2 = __uint_as_float(f2tf(p2));
        const float pf3 = __uint_as_float(f2tf(p3));
        lacc0 += pf0 + pf2;
        lacc1 += pf1 + pf3;
        *(float2*)&smP[r * 8 + 2 * c]       = make_float2(pf0, pf1);
        *(float2*)&smP[(r + 8) * 8 + 2 * c] = make_float2(pf2, pf3);
        __syncwarp();

        cp_wait2();             // VA done (VB, K_{st+1} may fly)
        bar_pair(barid);        // VA full (both warps)

        // ---------- PV chunk A: tokens 0-7 ----------
        {
            const uint32_t b0 = __float_as_uint(smP[c * 8 + r]);
            const uint32_t b1 = __float_as_uint(smP[(c + 4) * 8 + r]);
#pragma unroll
            for (int dt = 0; dt < 8; dt++) {
                uint32_t a0 = f2tf(vA0[16 * dt]);
                uint32_t a1 = f2tf(vA0[16 * dt + 8]);
                uint32_t a2 = f2tf(vA0[544 + 16 * dt]);
                uint32_t a3 = f2tf(vA0[544 + 16 * dt + 8]);
                mma_tf32(o0[dt], o1[dt], o2[dt], o3[dt], a0, a1, a2, a3, b0, b1);
            }
        }

        cp_wait1();             // VB done (K_{st+1} may fly)
        bar_pair(barid);        // VB full; both warps are past PV-A -> rows 0-7 dead

        // ---------- early VA prefetch for next sub-tile ----------
        if (st < 7) {
            issue_v(0, st + 1, blk_next);
            cp_commit();        // pending: [K_{st+1}, VA_{st+1}]  (loop invariant)
        }

        // ---------- PV chunk B: tokens 8-15 ----------
        {
            const uint32_t b0 = __float_as_uint(smP[64 + c * 8 + r]);
            const uint32_t b1 = __float_as_uint(smP[64 + (c + 4) * 8 + r]);
#pragma unroll
            for (int dt = 0; dt < 8; dt++) {
                uint32_t a0 = f2tf(vA0[1088 + 16 * dt]);
                uint32_t a1 = f2tf(vA0[1088 + 16 * dt + 8]);
                uint32_t a2 = f2tf(vA0[1632 + 16 * dt]);
                uint32_t a3 = f2tf(vA0[1632 + 16 * dt + 8]);
                mma_tf32(o0[dt], o1[dt], o2[dt], o3[dt], a0, a1, a2, a3, b0, b1);
            }
        }
        blk_cur = blk_next;
    }

    // ---------- finalize l: reduce across token-groups (lanes with same c) ----------
#pragma unroll
    for (int off = 4; off <= 16; off <<= 1) {
        lacc0 += __shfl_xor_sync(0xffffffffu, lacc0, off);
        lacc1 += __shfl_xor_sync(0xffffffffu, lacc1, off);
    }

    // ---------- cross-tile tree reduce (4 -> 1), per query-half ----------
    __syncthreads();
    float4* redo4 = (float4*)(sm_raw + OFF_K);   // dead K smem
    float*  redl  = (float*)(sm_raw + OFF_RL);
    for (int half = 2; half >= 1; half >>= 1) {
        if (tile >= half && tile < 2 * half) {
            const int idx = (tile - half) * 2 + qh;
#pragma unroll
            for (int dt = 0; dt < 8; dt++)
                redo4[(idx * 8 + dt) * 32 + lane] = make_float4(o0[dt], o1[dt], o2[dt], o3[dt]);
            if (lane < 4)
                *(float2*)&redl[idx * 8 + lane * 2] = make_float2(lacc0, lacc1);
        }
        __syncthreads();
        if (tile < half) {
            const int idx = tile * 2 + qh;
#pragma unroll
            for (int dt = 0; dt < 8; dt++) {
                float4 x = redo4[(idx * 8 + dt) * 32 + lane];
                o0[dt] += x.x; o1[dt] += x.y; o2[dt] += x.z; o3[dt] += x.w;
            }
            lacc0 += redl[idx * 8 + c * 2];
            lacc1 += redl[idx * 8 + c * 2 + 1];
        }
        __syncthreads();
    }

    // ---------- write per-split partials (warps 0 and 1) ----------
    if (tile == 0) {
        const size_t base = ((size_t)(s * 256) + b * 8 + h) * 2048;
#pragma unroll
        for (int dt = 0; dt < 8; dt++) {
            const int d0 = 16 * dt + r;
            *(float2*)&g_po[base + (size_t)d0 * 16 + qh * 8 + 2 * c] =
                make_float2(o0[dt], o1[dt]);
            *(float2*)&g_po[base + (size_t)(d0 + 8) * 16 + qh * 8 + 2 * c] =
                make_float2(o2[dt], o3[dt]);
        }
        if (lane < 4)
            *(float2*)&g_pl[(s * 256 + b * 8 + h) * 16 + qh * 8 + 2 * lane] =
                make_float2(lacc0, lacc1);
    }
}

// grid = 2048, block = 256
__global__ void __launch_bounds__(256) attn_combine(float* __restrict__ out)
{
    const int idx = blockIdx.x * 256 + threadIdx.x;
    const int qq  = idx & 15;
    const int dl  = (idx >> 4) & 127;
    const int bh  = idx >> 11;
    float acc = 0.f, l = 0.f;
#pragma unroll
    for (int ss = 0; ss < NSPLIT; ss++) {
        acc += __ldcs(&g_po[(size_t)ss * 524288 + (size_t)bh * 2048 + dl * 16 + qq]);
        l   += __ldcs(&g_pl[ss * 4096 + bh * 16 + qq]);
    }
    const int b = bh >> 3, hh = bh & 7, qpos = qq >> 2, g = qq & 3;
    out[(size_t)(b * 4 + qpos) * 4096 + (hh * 4 + g) * 128 + dl] = acc / l;
}

extern "C" void kernel_launch(void* const* d_in, const int* in_sizes, int n_in,
                              void* d_out, int out_size)
{
    const float* q   = (const float*)d_in[0];
    const float* k   = (const float*)d_in[1];
    const float* v   = (const float*)d_in[2];
    const float* kc  = (const float*)d_in[3];
    const float* vc  = (const float*)d_in[4];
    const int*   bt  = (const int*)d_in[5];
    (void)in_sizes; (void)n_in; (void)out_size;

    cudaFuncSetAttribute(attn_main, cudaFuncAttributeMaxDynamicSharedMemorySize, SMEM_TOTAL);
    attn_main<<<dim3(NSPLIT, 8, 32), 256, SMEM_TOTAL>>>(q, k, v, kc, vc, bt);
    attn_combine<<<2048, 256>>>((float*)d_out);
}